// round 9
// baseline (speedup 1.0000x reference)
#include <cuda_runtime.h>

#define FULLMASK 0xFFFFFFFFu

// Sum of squared differences of two 8-float (2x float4) chunks.
__device__ __forceinline__ float sd8(const float4& a0, const float4& a1,
                                     const float4& b0, const float4& b1) {
    float t, s;
    t = a0.x - b0.x; s = t * t;
    t = a0.y - b0.y; s = fmaf(t, t, s);
    t = a0.z - b0.z; s = fmaf(t, t, s);
    t = a0.w - b0.w; s = fmaf(t, t, s);
    t = a1.x - b1.x; s = fmaf(t, t, s);
    t = a1.y - b1.y; s = fmaf(t, t, s);
    t = a1.z - b1.z; s = fmaf(t, t, s);
    t = a1.w - b1.w; s = fmaf(t, t, s);
    return s;
}

// soft_rank with KL regularization, strength 2.0, n = 4 (register-resident).
__device__ __forceinline__ void softrank4(const float v[4], float out[4]) {
    float th[4];
    int pi[4];
#pragma unroll
    for (int m = 0; m < 4; m++) { th[m] = v[m] * 0.5f; pi[m] = m; }

    // descending sort network on 4 elems: (0,1)(2,3)(0,2)(1,3)(1,2)
#define CSWAP(a, b)                                     \
    do {                                                \
        if (th[a] < th[b]) {                            \
            float tf = th[a]; th[a] = th[b]; th[b] = tf;\
            int ti = pi[a]; pi[a] = pi[b]; pi[b] = ti;  \
        }                                               \
    } while (0)
    CSWAP(0, 1); CSWAP(2, 3); CSWAP(0, 2); CSWAP(1, 3); CSWAP(1, 2);
#undef CSWAP

    const float lcw00 = 1.3862943611198906f;  // log 4
    const float lcw01 = 1.9459101090932196f;  // log 7
    const float lcw02 = 2.1972245773362196f;  // log 9
    const float lcw03 = 2.302585092994046f;   // log 10
    const float lcw11 = 1.0986122886681098f;  // log 3
    const float lcw12 = 1.6094379124341003f;  // log 5
    const float lcw13 = 1.791759469228055f;   // log 6
    const float lcw22 = 0.6931471805599453f;  // log 2
    const float lcw23 = 1.0986122886681098f;  // log 3
    const float lcw33 = 0.0f;                 // log 1

    // B[i][j] = LSE(th[i..j]) - log(cw[i][j]); th descending so th[i] is seg max.
    float B[4][4];
    {
        float run;
        run = 1.0f;                       B[0][0] = th[0] - lcw00;
        run += __expf(th[1] - th[0]);     B[0][1] = th[0] + __logf(run) - lcw01;
        run += __expf(th[2] - th[0]);     B[0][2] = th[0] + __logf(run) - lcw02;
        run += __expf(th[3] - th[0]);     B[0][3] = th[0] + __logf(run) - lcw03;
        run = 1.0f;                       B[1][1] = th[1] - lcw11;
        run += __expf(th[2] - th[1]);     B[1][2] = th[1] + __logf(run) - lcw12;
        run += __expf(th[3] - th[1]);     B[1][3] = th[1] + __logf(run) - lcw13;
        run = 1.0f;                       B[2][2] = th[2] - lcw22;
        run += __expf(th[3] - th[2]);     B[2][3] = th[2] + __logf(run) - lcw23;
        B[3][3] = th[3] - lcw33;
    }

    // dual[k] = min_{i<=k} max_{j>=k} B[i][j]
    float dual[4];
    {
        float T0_3 = B[0][3], T0_2 = fmaxf(B[0][2], T0_3),
              T0_1 = fmaxf(B[0][1], T0_2), T0_0 = fmaxf(B[0][0], T0_1);
        float T1_3 = B[1][3], T1_2 = fmaxf(B[1][2], T1_3),
              T1_1 = fmaxf(B[1][1], T1_2);
        float T2_3 = B[2][3], T2_2 = fmaxf(B[2][2], T2_3);
        float T3_3 = B[3][3];
        dual[0] = T0_0;
        dual[1] = fminf(T0_1, T1_1);
        dual[2] = fminf(fminf(T0_2, T1_2), T2_2);
        dual[3] = fminf(fminf(T0_3, T1_3), fminf(T2_3, T3_3));
    }

#pragma unroll
    for (int k = 0; k < 4; k++) {
        float r = __expf(th[k] - dual[k]);
        out[0] = (pi[k] == 0) ? r : out[0];
        out[1] = (pi[k] == 1) ? r : out[1];
        out[2] = (pi[k] == 2) ? r : out[2];
        out[3] = (pi[k] == 3) ? r : out[3];
    }
}

__global__ void zero_out_kernel(float* out) { out[0] = 0.0f; }

// One block per id (512 blocks), 6 warps: warp = (feature t = w>>1, sub = w&1).
// Each warp loads 2 a-rows (rows 2*sub, 2*sub+1 of the half-0 group) plus all
// 4 b-rows (half-1 group) = 12 front-batched LDG.128, computes its 8 of the
// 16 (r,c) squared distances, reduce-scatters them in 16 SHFLs, and writes
// them to smem. After one sync, warp (t,0) soft-ranks the 4 half-0 queries
// and warp (t,1) the 4 half-1 queries — all 6 warps stay busy end-to-end.
// DRAM traffic unchanged (b-row duplicates hit cache inside the block).
__global__ void __launch_bounds__(192)
cmrr_main_kernel(const float* __restrict__ f0, const float* __restrict__ f1,
                 const float* __restrict__ f2, float* __restrict__ out) {
    __shared__ float dsm[3][4][4];   // [feature][r][c] distances
    __shared__ float4 rk_sh[3][8];   // [feature][query-slot] normalized ranks

    const int id = blockIdx.x;             // 0..511
    const int w = threadIdx.x >> 5;        // 0..5
    const int t = w >> 1;                  // feature 0..2
    const int sub = w & 1;                 // a-row pair: rows {2sub, 2sub+1}
    const int lane = threadIdx.x & 31;

    const int ib = id * 4;                 // half-0 rows
    const int jb = 2048 + id * 4;          // half-1 rows

    const float* __restrict__ f = (t == 0) ? f0 : ((t == 1) ? f1 : f2);

    // Cooperative load: lane owns elems {lane*4..+3} and {(lane+32)*4..+3}
    float4 fa[2][2], fb[4][2];
#pragma unroll
    for (int r = 0; r < 2; r++) {
        const float4* pa = reinterpret_cast<const float4*>(
            f + (size_t)(ib + 2 * sub + r) * 256);
        fa[r][0] = pa[lane];
        fa[r][1] = pa[lane + 32];
    }
#pragma unroll
    for (int c = 0; c < 4; c++) {
        const float4* pb =
            reinterpret_cast<const float4*>(f + (size_t)(jb + c) * 256);
        fb[c][0] = pb[lane];
        fb[c][1] = pb[lane + 32];
    }

    // 8 per-lane partials: p = r'*4 + c  (r' = local a-row 0..1)
    float s[8];
#pragma unroll
    for (int r = 0; r < 2; r++)
#pragma unroll
        for (int c = 0; c < 4; c++)
            s[r * 4 + c] = sd8(fa[r][0], fa[r][1], fb[c][0], fb[c][1]);

    // Stage A: combine the two 16-lane halves (8 SHFL).
#pragma unroll
    for (int k = 0; k < 8; k++) s[k] += __shfl_xor_sync(FULLMASK, s[k], 16);

    // Reduce-scatter 8 -> 1 value per lane (4+2+1+1 = 8 SHFL).
    // Final: lane l holds full sum of pair p = (l>>1) & 7.
    float myd2;
    {
        const bool up8 = (lane & 8) != 0;
        float t4[4];
#pragma unroll
        for (int k = 0; k < 4; k++) {
            float keep = up8 ? s[k + 4] : s[k];
            float snd = up8 ? s[k] : s[k + 4];
            t4[k] = keep + __shfl_xor_sync(FULLMASK, snd, 8);
        }
        const bool up4 = (lane & 4) != 0;
        float t2[2];
#pragma unroll
        for (int k = 0; k < 2; k++) {
            float keep = up4 ? t4[k + 2] : t4[k];
            float snd = up4 ? t4[k] : t4[k + 2];
            t2[k] = keep + __shfl_xor_sync(FULLMASK, snd, 4);
        }
        const bool up2 = (lane & 2) != 0;
        float keep = up2 ? t2[1] : t2[0];
        float snd = up2 ? t2[0] : t2[1];
        float t1 = keep + __shfl_xor_sync(FULLMASK, snd, 2);
        t1 += __shfl_xor_sync(FULLMASK, t1, 1);
        myd2 = t1;
    }

    // lanes 0,2,4,..,14 cover p = 0..7: global pair (r = 2*sub + p>>2, c = p&3)
    {
        float dist = sqrtf(fmaxf(myd2, 1e-12f));
        if (lane < 16 && (lane & 1) == 0) {
            int p = lane >> 1;
            dsm[t][2 * sub + (p >> 2)][p & 3] = dist;
        }
    }
    __syncthreads();

    // Soft-rank phase: warp (t,0) -> 4 half-0 queries (rows of D),
    //                  warp (t,1) -> 4 half-1 queries (cols of D).
    {
        const int rr = lane & 3;  // query slot within this warp's set
        float v[4];
#pragma unroll
        for (int c = 0; c < 4; c++)
            v[c] = (sub == 0) ? dsm[t][rr][c] : dsm[t][c][rr];

        float rk[4];
        softrank4(v, rk);

        float m = 0.25f * (rk[0] + rk[1] + rk[2] + rk[3]);
        float n2 = 0.0f;
#pragma unroll
        for (int c = 0; c < 4; c++) {
            rk[c] -= m;
            n2 = fmaf(rk[c], rk[c], n2);
        }
        float inv = rsqrtf(n2);
#pragma unroll
        for (int c = 0; c < 4; c++) rk[c] *= inv;

        if (lane < 4)
            rk_sh[t][sub * 4 + lane] = make_float4(rk[0], rk[1], rk[2], rk[3]);
    }
    __syncthreads();

    // warp 0: spearman across feature pairs for the 8 query slots, reduce,
    // accumulate the global mean.
    if (w == 0) {
        float loss = 0.0f;
        if (lane < 8) {
            float4 r0 = rk_sh[0][lane];
            float4 r1 = rk_sh[1][lane];
            float4 r2 = rk_sh[2][lane];
            float sp = r0.x * r1.x + r0.y * r1.y + r0.z * r1.z + r0.w * r1.w;
            sp += r0.x * r2.x + r0.y * r2.y + r0.z * r2.z + r0.w * r2.w;
            sp += r1.x * r2.x + r1.y * r2.y + r1.z * r2.z + r1.w * r2.w;
            loss = (sp + 3.0f) * (1.0f / 6.0f);
        }
        loss += __shfl_xor_sync(FULLMASK, loss, 1);
        loss += __shfl_xor_sync(FULLMASK, loss, 2);
        loss += __shfl_xor_sync(FULLMASK, loss, 4);
        if (lane == 0) atomicAdd(out, loss * (1.0f / 4096.0f));
    }
}

extern "C" void kernel_launch(void* const* d_in, const int* in_sizes, int n_in,
                              void* d_out, int out_size) {
    const float* f0 = (const float*)d_in[0];
    const float* f1 = (const float*)d_in[1];
    const float* f2 = (const float*)d_in[2];
    float* out = (float*)d_out;

    zero_out_kernel<<<1, 1>>>(out);
    cmrr_main_kernel<<<512, 192>>>(f0, f1, f2, out);
}

// round 10
// speedup vs baseline: 1.0295x; 1.0295x over previous
#include <cuda_runtime.h>

#define FULLMASK 0xFFFFFFFFu

// Sum of squared differences of two 8-float (2x float4) chunks.
__device__ __forceinline__ float sd8(const float4& a0, const float4& a1,
                                     const float4& b0, const float4& b1) {
    float t, s;
    t = a0.x - b0.x; s = t * t;
    t = a0.y - b0.y; s = fmaf(t, t, s);
    t = a0.z - b0.z; s = fmaf(t, t, s);
    t = a0.w - b0.w; s = fmaf(t, t, s);
    t = a1.x - b1.x; s = fmaf(t, t, s);
    t = a1.y - b1.y; s = fmaf(t, t, s);
    t = a1.z - b1.z; s = fmaf(t, t, s);
    t = a1.w - b1.w; s = fmaf(t, t, s);
    return s;
}

// soft_rank with KL regularization, strength 2.0, n = 4 (register-resident).
__device__ __forceinline__ void softrank4(const float v[4], float out[4]) {
    float th[4];
    int pi[4];
#pragma unroll
    for (int m = 0; m < 4; m++) { th[m] = v[m] * 0.5f; pi[m] = m; }

    // descending sort network on 4 elems: (0,1)(2,3)(0,2)(1,3)(1,2)
#define CSWAP(a, b)                                     \
    do {                                                \
        if (th[a] < th[b]) {                            \
            float tf = th[a]; th[a] = th[b]; th[b] = tf;\
            int ti = pi[a]; pi[a] = pi[b]; pi[b] = ti;  \
        }                                               \
    } while (0)
    CSWAP(0, 1); CSWAP(2, 3); CSWAP(0, 2); CSWAP(1, 3); CSWAP(1, 2);
#undef CSWAP

    const float lcw00 = 1.3862943611198906f;  // log 4
    const float lcw01 = 1.9459101090932196f;  // log 7
    const float lcw02 = 2.1972245773362196f;  // log 9
    const float lcw03 = 2.302585092994046f;   // log 10
    const float lcw11 = 1.0986122886681098f;  // log 3
    const float lcw12 = 1.6094379124341003f;  // log 5
    const float lcw13 = 1.791759469228055f;   // log 6
    const float lcw22 = 0.6931471805599453f;  // log 2
    const float lcw23 = 1.0986122886681098f;  // log 3
    const float lcw33 = 0.0f;                 // log 1

    // B[i][j] = LSE(th[i..j]) - log(cw[i][j]); th descending so th[i] is seg max.
    float B[4][4];
    {
        float run;
        run = 1.0f;                       B[0][0] = th[0] - lcw00;
        run += __expf(th[1] - th[0]);     B[0][1] = th[0] + __logf(run) - lcw01;
        run += __expf(th[2] - th[0]);     B[0][2] = th[0] + __logf(run) - lcw02;
        run += __expf(th[3] - th[0]);     B[0][3] = th[0] + __logf(run) - lcw03;
        run = 1.0f;                       B[1][1] = th[1] - lcw11;
        run += __expf(th[2] - th[1]);     B[1][2] = th[1] + __logf(run) - lcw12;
        run += __expf(th[3] - th[1]);     B[1][3] = th[1] + __logf(run) - lcw13;
        run = 1.0f;                       B[2][2] = th[2] - lcw22;
        run += __expf(th[3] - th[2]);     B[2][3] = th[2] + __logf(run) - lcw23;
        B[3][3] = th[3] - lcw33;
    }

    // dual[k] = min_{i<=k} max_{j>=k} B[i][j]
    float dual[4];
    {
        float T0_3 = B[0][3], T0_2 = fmaxf(B[0][2], T0_3),
              T0_1 = fmaxf(B[0][1], T0_2), T0_0 = fmaxf(B[0][0], T0_1);
        float T1_3 = B[1][3], T1_2 = fmaxf(B[1][2], T1_3),
              T1_1 = fmaxf(B[1][1], T1_2);
        float T2_3 = B[2][3], T2_2 = fmaxf(B[2][2], T2_3);
        float T3_3 = B[3][3];
        dual[0] = T0_0;
        dual[1] = fminf(T0_1, T1_1);
        dual[2] = fminf(fminf(T0_2, T1_2), T2_2);
        dual[3] = fminf(fminf(T0_3, T1_3), fminf(T2_3, T3_3));
    }

#pragma unroll
    for (int k = 0; k < 4; k++) {
        float r = __expf(th[k] - dual[k]);
        out[0] = (pi[k] == 0) ? r : out[0];
        out[1] = (pi[k] == 1) ? r : out[1];
        out[2] = (pi[k] == 2) ? r : out[2];
        out[3] = (pi[k] == 3) ? r : out[3];
    }
}

// Full distance->softrank->normalize pipeline for one id's 8 rows.
// Returns the normalized rank float4 for this lane's query (lanes 0..7).
__device__ __forceinline__ float4 compute_rank(const float4 (&fa)[4][2],
                                               const float4 (&fb)[4][2],
                                               int lane) {
    // d2 partial k = r*4+c
    float s[16];
#pragma unroll
    for (int r = 0; r < 4; r++)
#pragma unroll
        for (int c = 0; c < 4; c++)
            s[r * 4 + c] = sd8(fa[r][0], fa[r][1], fb[c][0], fb[c][1]);

    // Stage 1: combine the two 16-lane halves (16 SHFL).
#pragma unroll
    for (int k = 0; k < 16; k++)
        s[k] += __shfl_xor_sync(FULLMASK, s[k], 16);

    // Reduce-scatter: lane l ends holding the full sum of pair (l & 15).
    float myd2;
    {
        const bool up8 = (lane & 8) != 0;
        float t8[8];
#pragma unroll
        for (int k = 0; k < 8; k++) {
            float keep = up8 ? s[k + 8] : s[k];
            float snd = up8 ? s[k] : s[k + 8];
            t8[k] = keep + __shfl_xor_sync(FULLMASK, snd, 8);
        }
        const bool up4 = (lane & 4) != 0;
        float t4[4];
#pragma unroll
        for (int k = 0; k < 4; k++) {
            float keep = up4 ? t8[k + 4] : t8[k];
            float snd = up4 ? t8[k] : t8[k + 4];
            t4[k] = keep + __shfl_xor_sync(FULLMASK, snd, 4);
        }
        const bool up2 = (lane & 2) != 0;
        float t2[2];
#pragma unroll
        for (int k = 0; k < 2; k++) {
            float keep = up2 ? t4[k + 2] : t4[k];
            float snd = up2 ? t4[k] : t4[k + 2];
            t2[k] = keep + __shfl_xor_sync(FULLMASK, snd, 2);
        }
        const bool up1 = (lane & 1) != 0;
        float keep = up1 ? t2[1] : t2[0];
        float snd = up1 ? t2[0] : t2[1];
        myd2 = keep + __shfl_xor_sync(FULLMASK, snd, 1);
    }

    float dist = sqrtf(fmaxf(myd2, 1e-12f));

    // lanes 0..3: half-0 query l,   v[c] = dist(l, c)   (src = l*4+c)
    // lanes 4..7: half-1 query l-4, v[c] = dist(c, l-4) (src = c*4+(l-4))
    const int rr = lane & 3;
    const bool trans = (lane & 4) != 0;
    float v[4];
#pragma unroll
    for (int c = 0; c < 4; c++) {
        int src = trans ? (c * 4 + rr) : (rr * 4 + c);
        v[c] = __shfl_sync(FULLMASK, dist, src);
    }

    float rk[4];
    softrank4(v, rk);

    float m = 0.25f * (rk[0] + rk[1] + rk[2] + rk[3]);
    float n2 = 0.0f;
#pragma unroll
    for (int c = 0; c < 4; c++) {
        rk[c] -= m;
        n2 = fmaf(rk[c], rk[c], n2);
    }
    float inv = rsqrtf(n2);
    return make_float4(rk[0] * inv, rk[1] * inv, rk[2] * inv, rk[3] * inv);
}

__global__ void zero_out_kernel(float* out) { out[0] = 0.0f; }

// 256 blocks x 3 warps (one per feature). Each block handles TWO ids
// (2*bx, 2*bx+1). All 32 LDG.128 per warp are front-batched: while id A's
// reduce/softrank executes, id B's loads are still in flight, hiding B's
// DRAM latency behind A's compute. DRAM traffic unchanged (every row once).
__global__ void __launch_bounds__(96)
cmrr_main_kernel(const float* __restrict__ f0, const float* __restrict__ f1,
                 const float* __restrict__ f2, float* __restrict__ out) {
    __shared__ float4 rk_sh[3][16];  // [feature][idslot*8 + query-slot]

    const int bx = blockIdx.x;            // 0..255
    const int t = threadIdx.x >> 5;       // feature 0..2
    const int lane = threadIdx.x & 31;

    const float* __restrict__ f = (t == 0) ? f0 : ((t == 1) ? f1 : f2);

    // id A = 2*bx: half-0 rows 8bx..+3, half-1 rows 2048+8bx..+3
    // id B = 2*bx+1: the next 4 rows in each half
    const int ibA = bx * 8;
    const int jbA = 2048 + bx * 8;

    float4 Aa[4][2], Ab[4][2], Ba[4][2], Bb[4][2];
#pragma unroll
    for (int r = 0; r < 4; r++) {
        const float4* pa =
            reinterpret_cast<const float4*>(f + (size_t)(ibA + r) * 256);
        const float4* pb =
            reinterpret_cast<const float4*>(f + (size_t)(jbA + r) * 256);
        Aa[r][0] = pa[lane];
        Aa[r][1] = pa[lane + 32];
        Ab[r][0] = pb[lane];
        Ab[r][1] = pb[lane + 32];
    }
#pragma unroll
    for (int r = 0; r < 4; r++) {
        const float4* pa =
            reinterpret_cast<const float4*>(f + (size_t)(ibA + 4 + r) * 256);
        const float4* pb =
            reinterpret_cast<const float4*>(f + (size_t)(jbA + 4 + r) * 256);
        Ba[r][0] = pa[lane];
        Ba[r][1] = pa[lane + 32];
        Bb[r][0] = pb[lane];
        Bb[r][1] = pb[lane + 32];
    }

    // id A compute (B's loads still in flight underneath)
    float4 rkA = compute_rank(Aa, Ab, lane);
    if (lane < 8) rk_sh[t][lane] = rkA;

    // id B compute
    float4 rkB = compute_rank(Ba, Bb, lane);
    if (lane < 8) rk_sh[t][8 + lane] = rkB;

    __syncthreads();

    // warp 0: spearman for all 16 query slots (both ids), one atomic.
    if (t == 0) {
        float loss = 0.0f;
        if (lane < 16) {
            float4 r0 = rk_sh[0][lane];
            float4 r1 = rk_sh[1][lane];
            float4 r2 = rk_sh[2][lane];
            float sp = r0.x * r1.x + r0.y * r1.y + r0.z * r1.z + r0.w * r1.w;
            sp += r0.x * r2.x + r0.y * r2.y + r0.z * r2.z + r0.w * r2.w;
            sp += r1.x * r2.x + r1.y * r2.y + r1.z * r2.z + r1.w * r2.w;
            loss = (sp + 3.0f) * (1.0f / 6.0f);
        }
        loss += __shfl_xor_sync(FULLMASK, loss, 1);
        loss += __shfl_xor_sync(FULLMASK, loss, 2);
        loss += __shfl_xor_sync(FULLMASK, loss, 4);
        loss += __shfl_xor_sync(FULLMASK, loss, 8);
        if (lane == 0) atomicAdd(out, loss * (1.0f / 4096.0f));
    }
}

extern "C" void kernel_launch(void* const* d_in, const int* in_sizes, int n_in,
                              void* d_out, int out_size) {
    const float* f0 = (const float*)d_in[0];
    const float* f1 = (const float*)d_in[1];
    const float* f2 = (const float*)d_in[2];
    float* out = (float*)d_out;

    zero_out_kernel<<<1, 1>>>(out);
    cmrr_main_kernel<<<256, 96>>>(f0, f1, f2, out);
}

// round 11
// speedup vs baseline: 1.0856x; 1.0545x over previous
#include <cuda_runtime.h>

#define FULLMASK 0xFFFFFFFFu

// Sum of squared differences of two 8-float (2x float4) chunks.
__device__ __forceinline__ float sd8(const float4& a0, const float4& a1,
                                     const float4& b0, const float4& b1) {
    float t, s;
    t = a0.x - b0.x; s = t * t;
    t = a0.y - b0.y; s = fmaf(t, t, s);
    t = a0.z - b0.z; s = fmaf(t, t, s);
    t = a0.w - b0.w; s = fmaf(t, t, s);
    t = a1.x - b1.x; s = fmaf(t, t, s);
    t = a1.y - b1.y; s = fmaf(t, t, s);
    t = a1.z - b1.z; s = fmaf(t, t, s);
    t = a1.w - b1.w; s = fmaf(t, t, s);
    return s;
}

// soft_rank with KL regularization, strength 2.0, n = 4 (register-resident).
__device__ __forceinline__ void softrank4(const float v[4], float out[4]) {
    float th[4];
    int pi[4];
#pragma unroll
    for (int m = 0; m < 4; m++) { th[m] = v[m] * 0.5f; pi[m] = m; }

    // descending sort network on 4 elems: (0,1)(2,3)(0,2)(1,3)(1,2)
#define CSWAP(a, b)                                     \
    do {                                                \
        if (th[a] < th[b]) {                            \
            float tf = th[a]; th[a] = th[b]; th[b] = tf;\
            int ti = pi[a]; pi[a] = pi[b]; pi[b] = ti;  \
        }                                               \
    } while (0)
    CSWAP(0, 1); CSWAP(2, 3); CSWAP(0, 2); CSWAP(1, 3); CSWAP(1, 2);
#undef CSWAP

    const float lcw00 = 1.3862943611198906f;  // log 4
    const float lcw01 = 1.9459101090932196f;  // log 7
    const float lcw02 = 2.1972245773362196f;  // log 9
    const float lcw03 = 2.302585092994046f;   // log 10
    const float lcw11 = 1.0986122886681098f;  // log 3
    const float lcw12 = 1.6094379124341003f;  // log 5
    const float lcw13 = 1.791759469228055f;   // log 6
    const float lcw22 = 0.6931471805599453f;  // log 2
    const float lcw23 = 1.0986122886681098f;  // log 3
    const float lcw33 = 0.0f;                 // log 1

    // B[i][j] = LSE(th[i..j]) - log(cw[i][j]); th descending so th[i] is seg max.
    float B[4][4];
    {
        float run;
        run = 1.0f;                       B[0][0] = th[0] - lcw00;
        run += __expf(th[1] - th[0]);     B[0][1] = th[0] + __logf(run) - lcw01;
        run += __expf(th[2] - th[0]);     B[0][2] = th[0] + __logf(run) - lcw02;
        run += __expf(th[3] - th[0]);     B[0][3] = th[0] + __logf(run) - lcw03;
        run = 1.0f;                       B[1][1] = th[1] - lcw11;
        run += __expf(th[2] - th[1]);     B[1][2] = th[1] + __logf(run) - lcw12;
        run += __expf(th[3] - th[1]);     B[1][3] = th[1] + __logf(run) - lcw13;
        run = 1.0f;                       B[2][2] = th[2] - lcw22;
        run += __expf(th[3] - th[2]);     B[2][3] = th[2] + __logf(run) - lcw23;
        B[3][3] = th[3] - lcw33;
    }

    // dual[k] = min_{i<=k} max_{j>=k} B[i][j]
    float dual[4];
    {
        float T0_3 = B[0][3], T0_2 = fmaxf(B[0][2], T0_3),
              T0_1 = fmaxf(B[0][1], T0_2), T0_0 = fmaxf(B[0][0], T0_1);
        float T1_3 = B[1][3], T1_2 = fmaxf(B[1][2], T1_3),
              T1_1 = fmaxf(B[1][1], T1_2);
        float T2_3 = B[2][3], T2_2 = fmaxf(B[2][2], T2_3);
        float T3_3 = B[3][3];
        dual[0] = T0_0;
        dual[1] = fminf(T0_1, T1_1);
        dual[2] = fminf(fminf(T0_2, T1_2), T2_2);
        dual[3] = fminf(fminf(T0_3, T1_3), fminf(T2_3, T3_3));
    }

#pragma unroll
    for (int k = 0; k < 4; k++) {
        float r = __expf(th[k] - dual[k]);
        out[0] = (pi[k] == 0) ? r : out[0];
        out[1] = (pi[k] == 1) ? r : out[1];
        out[2] = (pi[k] == 2) ? r : out[2];
        out[3] = (pi[k] == 3) ? r : out[3];
    }
}

// One block per id (512 blocks), 3 warps = one per feature — the best
// measured main kernel (6.69us): 16 front-batched LDG.128 per warp,
// 31-SHFL reduce-scatter (lane l < 16 ends holding the full sum of
// d2[l>>2][l&3], replicated in the upper half-warp) + 4-SHFL gather.
__global__ void __launch_bounds__(96)
cmrr_main_kernel(const float* __restrict__ f0, const float* __restrict__ f1,
                 const float* __restrict__ f2, float* __restrict__ out) {
    __shared__ float4 sh[3][8];  // [feature][row-slot] -> normalized ranks

    const int id = blockIdx.x;            // 0..511
    const int t = threadIdx.x >> 5;       // feature 0..2
    const int lane = threadIdx.x & 31;

    const int ib = id * 4;                // half-0 rows
    const int jb = 2048 + id * 4;         // half-1 rows

    const float* __restrict__ f = (t == 0) ? f0 : ((t == 1) ? f1 : f2);

    // Cooperative load: lane owns elems {lane*4..+3} and {(lane+32)*4..+3}
    float4 fa[4][2], fb[4][2];
#pragma unroll
    for (int r = 0; r < 4; r++) {
        const float4* pa =
            reinterpret_cast<const float4*>(f + (size_t)(ib + r) * 256);
        const float4* pb =
            reinterpret_cast<const float4*>(f + (size_t)(jb + r) * 256);
        fa[r][0] = pa[lane];
        fa[r][1] = pa[lane + 32];
        fb[r][0] = pb[lane];
        fb[r][1] = pb[lane + 32];
    }

    // d2 partial k = r*4+c: sum over this lane's 8 dims of (a_r - b_c)^2
    float s[16];
#pragma unroll
    for (int r = 0; r < 4; r++)
#pragma unroll
        for (int c = 0; c < 4; c++)
            s[r * 4 + c] = sd8(fa[r][0], fa[r][1], fb[c][0], fb[c][1]);

    // Stage 1: combine the two 16-lane halves (butterfly; both sides add).
#pragma unroll
    for (int k = 0; k < 16; k++)
        s[k] += __shfl_xor_sync(FULLMASK, s[k], 16);

    // Stages 2-5: reduce-scatter within each 16-lane half. After them,
    // lane l holds the full sum of value (l & 15); upper half replicates.
    float myd2;
    {
        const bool up8 = (lane & 8) != 0;
        float t8[8];
#pragma unroll
        for (int k = 0; k < 8; k++) {
            float keep = up8 ? s[k + 8] : s[k];
            float snd = up8 ? s[k] : s[k + 8];
            t8[k] = keep + __shfl_xor_sync(FULLMASK, snd, 8);
        }
        const bool up4 = (lane & 4) != 0;
        float t4[4];
#pragma unroll
        for (int k = 0; k < 4; k++) {
            float keep = up4 ? t8[k + 4] : t8[k];
            float snd = up4 ? t8[k] : t8[k + 4];
            t4[k] = keep + __shfl_xor_sync(FULLMASK, snd, 4);
        }
        const bool up2 = (lane & 2) != 0;
        float t2[2];
#pragma unroll
        for (int k = 0; k < 2; k++) {
            float keep = up2 ? t4[k + 2] : t4[k];
            float snd = up2 ? t4[k] : t4[k + 2];
            t2[k] = keep + __shfl_xor_sync(FULLMASK, snd, 2);
        }
        const bool up1 = (lane & 1) != 0;
        float keep = up1 ? t2[1] : t2[0];
        float snd = up1 ? t2[0] : t2[1];
        myd2 = keep + __shfl_xor_sync(FULLMASK, snd, 1);
    }

    // lane l (l mod 16 = r*4+c) -> distance for pair (r, c)
    float dist = sqrtf(fmaxf(myd2, 1e-12f));

    // lanes 0..3: query row ib+l,   v[c] = dist(l, c)   (src = l*4+c)
    // lanes 4..7: query row jb+(l-4), v[c] = dist(c, l-4) (src = c*4+(l-4))
    const int rr = lane & 3;
    const bool trans = (lane & 4) != 0;
    float v[4];
#pragma unroll
    for (int c = 0; c < 4; c++) {
        int src = trans ? (c * 4 + rr) : (rr * 4 + c);
        v[c] = __shfl_sync(FULLMASK, dist, src);
    }

    float rk[4];
    softrank4(v, rk);

    // center + normalize
    {
        float m = 0.25f * (rk[0] + rk[1] + rk[2] + rk[3]);
        float n2 = 0.0f;
#pragma unroll
        for (int c = 0; c < 4; c++) {
            rk[c] -= m;
            n2 = fmaf(rk[c], rk[c], n2);
        }
        float inv = rsqrtf(n2);
#pragma unroll
        for (int c = 0; c < 4; c++) rk[c] *= inv;
    }

    if (lane < 8) sh[t][lane] = make_float4(rk[0], rk[1], rk[2], rk[3]);
    __syncthreads();

    // warp 0: spearman across feature pairs for the 8 query rows, reduce,
    // accumulate the global mean.
    if (t == 0) {
        float loss = 0.0f;
        if (lane < 8) {
            float4 r0 = sh[0][lane];
            float4 r1 = sh[1][lane];
            float4 r2 = sh[2][lane];
            float sp = r0.x * r1.x + r0.y * r1.y + r0.z * r1.z + r0.w * r1.w;
            sp += r0.x * r2.x + r0.y * r2.y + r0.z * r2.z + r0.w * r2.w;
            sp += r1.x * r2.x + r1.y * r2.y + r1.z * r2.z + r1.w * r2.w;
            loss = (sp + 3.0f) * (1.0f / 6.0f);
        }
        loss += __shfl_xor_sync(FULLMASK, loss, 1);
        loss += __shfl_xor_sync(FULLMASK, loss, 2);
        loss += __shfl_xor_sync(FULLMASK, loss, 4);
        if (lane == 0) atomicAdd(out, loss * (1.0f / 4096.0f));
    }
}

extern "C" void kernel_launch(void* const* d_in, const int* in_sizes, int n_in,
                              void* d_out, int out_size) {
    const float* f0 = (const float*)d_in[0];
    const float* f1 = (const float*)d_in[1];
    const float* f2 = (const float*)d_in[2];
    float* out = (float*)d_out;

    // Zero the accumulator via an async memset node (cheaper than a kernel
    // launch; graph-capturable, allocation-free).
    cudaMemsetAsync(out, 0, sizeof(float), 0);
    cmrr_main_kernel<<<512, 96>>>(f0, f1, f2, out);
}